// round 3
// baseline (speedup 1.0000x reference)
#include <cuda_runtime.h>

// Problem constants (fixed by the dataset)
#define NND   65536     // nodes
#define EED   524288    // edges
#define BBD   256       // graphs
#define GSD   256       // nodes per graph (contiguous: graph = node >> 8)
#define EMBD  128
#define FEATD 64

// ---------------- scratch (static __device__ globals; no allocation) ----------------
__device__ float g_cur[NND * EMBD];     // current node features
__device__ float g_new[NND * EMBD];     // conv0 pre-BN output / per-block "new" buffer
__device__ float g_agg0[NND * FEATD];   // conv0 max-aggregation
__device__ int   g_off[NND + 1];        // CSR offsets (edges sorted by dst)
__device__ int   g_cnt[NND];            // histogram / scatter cursor
__device__ int   g_srcs[EED];           // CSR src list
__device__ int   g_bsum[256];           // scan block sums
__device__ float g_score[4 * NND];
__device__ float g_sm[4 * NND];
__device__ unsigned char g_keep[4 * NND];
__device__ int   g_klist[4 * NND];
__device__ int   g_kcount[4];
__device__ float g_gate[4 * NND];
__device__ float g_partS[128 * EMBD];   // column-stat partials [chunk][col]
__device__ float g_partQ[128 * EMBD];
__device__ float g_mean[EMBD];
__device__ float g_gamrs[EMBD];         // gamma * rsqrt(var + eps)
__device__ float g_pooled[4 * BBD * EMBD];
__device__ float g_logits[BBD * 4];

__device__ __forceinline__ float lrelu(float v) { return v > 0.f ? v : 0.01f * v; }

// ---------------- CSR build (counting sort of edges by dst) ----------------
__global__ void k_zero_cnt() {
    int i = blockIdx.x * 256 + threadIdx.x;
    g_cnt[i] = 0;
}

__global__ void k_hist(const int* __restrict__ dst) {
    int e = blockIdx.x * 256 + threadIdx.x;
    atomicAdd(&g_cnt[dst[e]], 1);
}

__global__ void k_scan1() {  // per-block (256 elems) exclusive scan + block totals
    __shared__ int sh[256];
    int b = blockIdx.x, t = threadIdx.x;
    int v = g_cnt[b * 256 + t];
    sh[t] = v; __syncthreads();
    for (int ofs = 1; ofs < 256; ofs <<= 1) {
        int add = (t >= ofs) ? sh[t - ofs] : 0;
        __syncthreads();
        sh[t] += add;
        __syncthreads();
    }
    g_off[b * 256 + t] = sh[t] - v;
    if (t == 255) g_bsum[b] = sh[255];
}

__global__ void k_scan2() {  // exclusive scan of 256 block sums
    __shared__ int sh[256];
    int t = threadIdx.x;
    int v = g_bsum[t];
    sh[t] = v; __syncthreads();
    for (int ofs = 1; ofs < 256; ofs <<= 1) {
        int add = (t >= ofs) ? sh[t - ofs] : 0;
        __syncthreads();
        sh[t] += add;
        __syncthreads();
    }
    g_bsum[t] = sh[t] - v;
}

__global__ void k_scan3() {
    int i = blockIdx.x * 256 + threadIdx.x;
    g_off[i] += g_bsum[i >> 8];
    g_cnt[i] = 0;                       // becomes scatter cursor
    if (i == 0) g_off[NND] = EED;
}

__global__ void k_scatter(const int* __restrict__ src, const int* __restrict__ dst) {
    int e = blockIdx.x * 256 + threadIdx.x;
    int d = dst[e];
    int p = atomicAdd(&g_cnt[d], 1);
    g_srcs[g_off[d] + p] = src[e];
}

// ---------------- conv0: warp-per-node max aggregation over in-edges ----------------
__global__ void k_agg0(const float* __restrict__ x) {
    int warp = (blockIdx.x * blockDim.x + threadIdx.x) >> 5;
    int lane = threadIdx.x & 31;
    if (warp >= NND) return;
    int o = g_off[warp], c = g_off[warp + 1] - o;
    float m0 = -3.402823466e38f, m1 = m0;
    for (int j = 0; j < c; j++) {
        int s = g_srcs[o + j];
        m0 = fmaxf(m0, x[s * FEATD + lane]);
        m1 = fmaxf(m1, x[s * FEATD + 32 + lane]);
    }
    g_agg0[warp * FEATD + lane]      = c ? m0 : 0.f;  // no in-edges -> 0 (PyG fill)
    g_agg0[warp * FEATD + 32 + lane] = c ? m1 : 0.f;
}

// ---------------- conv0 GEMM: h = lrelu(agg@Wrel.T + x@Wroot.T + b) ----------------
// block: 256 threads, 64 nodes; smem: transposed weights (2x32KB) + node rows (2x16KB)
__global__ void __launch_bounds__(256) k_conv0(const float* __restrict__ x,
                                               const float* __restrict__ Wrel,
                                               const float* __restrict__ Wroot,
                                               const float* __restrict__ bias) {
    extern __shared__ float sh[];
    float* s_wr = sh;                  // [64][128] (k-major, f contiguous)
    float* s_wo = sh + 64 * 128;
    float* s_a  = sh + 2 * 64 * 128;   // [64 nodes][64]
    float* s_x  = s_a + 64 * 64;
    int t = threadIdx.x;
    for (int idx = t; idx < 128 * 64; idx += 256) {
        int f = idx >> 6, k = idx & 63;
        s_wr[k * 128 + f] = Wrel[idx];
        s_wo[k * 128 + f] = Wroot[idx];
    }
    int nbase = blockIdx.x * 64;
    for (int idx = t; idx < 64 * 64; idx += 256) {
        s_a[idx] = g_agg0[nbase * 64 + idx];
        s_x[idx] = x[nbase * 64 + idx];
    }
    __syncthreads();
    int f = t & 127, half = t >> 7;
    float acc[32];
    float bb = bias[f];
#pragma unroll
    for (int j = 0; j < 32; j++) acc[j] = bb;
    for (int k = 0; k < 64; k++) {
        float wr = s_wr[k * 128 + f], wo = s_wo[k * 128 + f];
#pragma unroll
        for (int j = 0; j < 32; j++) {
            int n = half * 32 + j;
            acc[j] += s_a[n * 64 + k] * wr + s_x[n * 64 + k] * wo;
        }
    }
#pragma unroll
    for (int j = 0; j < 32; j++) {
        int n = half * 32 + j;
        g_new[(nbase + n) * EMBD + f] = lrelu(acc[j]);
    }
}

// ---------------- deterministic column stats (mean/var over N rows) ----------------
__global__ void k_colstats() {  // grid 128 chunks x 128 threads; reads g_new
    int chunk = blockIdx.x, col = threadIdx.x;
    float s = 0.f, q = 0.f;
    const float* p = g_new + (size_t)chunk * 512 * EMBD;
    for (int r = 0; r < 512; r++) {
        float v = p[r * EMBD + col];
        s += v; q += v * v;
    }
    g_partS[chunk * EMBD + col] = s;
    g_partQ[chunk * EMBD + col] = q;
}

__global__ void k_colfinal(const float* __restrict__ gamma) {  // 1 block x 128
    int col = threadIdx.x;
    float s = 0.f, q = 0.f;
    for (int c = 0; c < 128; c++) { s += g_partS[c * EMBD + col]; q += g_partQ[c * EMBD + col]; }
    float mean = s / (float)NND;
    float var  = q / (float)NND - mean * mean;
    g_mean[col]  = mean;
    g_gamrs[col] = gamma[col] * rsqrtf(var + 1e-5f);
}

__global__ void k_bn_apply(const float* __restrict__ beta) {  // cur = bn(new)
    int i = blockIdx.x * 256 + threadIdx.x;
    int f = i & 127;
    g_cur[i] = (g_new[i] - g_mean[f]) * g_gamrs[f] + beta[f];
}

__global__ void k_residual(const float* __restrict__ beta) {  // cur = 0.5*cur + 0.25*bn(new)
    int i = blockIdx.x * 256 + threadIdx.x;
    int f = i & 127;
    g_cur[i] = 0.5f * g_cur[i] + 0.25f * ((g_new[i] - g_mean[f]) * g_gamrs[f] + beta[f]);
}

// ---------------- pooling: 4 scores per node in one pass ----------------
__global__ void k_init4() { if (threadIdx.x < 4) g_kcount[threadIdx.x] = 0; }

__global__ void k_scores(const float* __restrict__ w4) {  // w4: [4][128]
    __shared__ float sw[512];
    int t = threadIdx.x;
    for (int i = t; i < 512; i += 256) sw[i] = w4[i];
    __syncthreads();
    int warp = blockIdx.x * 8 + (t >> 5);
    int lane = t & 31;
    float4 c4 = *reinterpret_cast<const float4*>(g_cur + warp * 128 + lane * 4);
#pragma unroll
    for (int h = 0; h < 4; h++) {
        const float* w = sw + h * 128 + lane * 4;
        float p = c4.x * w[0] + c4.y * w[1] + c4.z * w[2] + c4.w * w[3];
        for (int o = 16; o > 0; o >>= 1) p += __shfl_xor_sync(0xffffffffu, p, o);
        if (lane == 0) g_score[h * NND + warp] = p;
    }
}

// per-graph softmax, keep mask (thr = min(smax-1e-7, min_score)), compaction
__global__ void k_softmax(float minscore) {  // grid (B, 4) x 256
    __shared__ float red[256];
    int g = blockIdx.x, h = blockIdx.y, t = threadIdx.x;
    int i = g * 256 + t;
    float s = g_score[h * NND + i];
    red[t] = s; __syncthreads();
    for (int st = 128; st > 0; st >>= 1) { if (t < st) red[t] = fmaxf(red[t], red[t + st]); __syncthreads(); }
    float m = red[0]; __syncthreads();
    float e = expf(s - m);
    red[t] = e; __syncthreads();
    for (int st = 128; st > 0; st >>= 1) { if (t < st) red[t] += red[t + st]; __syncthreads(); }
    float S = red[0]; __syncthreads();
    float sm = e / (S + 1e-16f);
    red[t] = sm; __syncthreads();
    for (int st = 128; st > 0; st >>= 1) { if (t < st) red[t] = fmaxf(red[t], red[t + st]); __syncthreads(); }
    float smax = red[0];
    float thr = fminf(smax - 1e-7f, minscore);
    bool keep = sm > thr;
    g_sm[h * NND + i] = sm;
    g_keep[h * NND + i] = keep ? 1 : 0;
    if (keep) { int p = atomicAdd(&g_kcount[h], 1); g_klist[h * NND + p] = i; }
}

__global__ void k_zero_new() {
    int i = blockIdx.x * 256 + threadIdx.x;
    reinterpret_cast<float4*>(g_new)[i] = make_float4(0.f, 0.f, 0.f, 0.f);
}

// ---------------- block head conv on kept nodes only (warp per kept node) ----------------
__global__ void k_head_out(const float* __restrict__ Wrel, const float* __restrict__ Wroot,
                           const float* __restrict__ bias) {  // grid (256, 4) x 256
    __shared__ float s_agg[8][128];
    __shared__ float s_xp[8][128];
    int h = blockIdx.y;
    int kc = g_kcount[h];
    int w = threadIdx.x >> 5, lane = threadIdx.x & 31;
    const float* smh = g_sm + h * NND;
    const unsigned char* kph = g_keep + h * NND;
    for (int entry = blockIdx.x * 8 + w; entry < kc; entry += gridDim.x * 8) {
        int i = g_klist[h * NND + entry];
        int o = g_off[i];
        int c = g_off[i + 1] - o;
        float a0 = -3.402823466e38f, a1 = a0, a2 = a0, a3 = a0;
        bool any = false;
        for (int j = 0; j < c; j++) {
            int s = g_srcs[o + j];
            if (kph[s]) {                 // uniform branch within warp
                any = true;
                float ss = smh[s];
                const float* cr = g_cur + s * 128;
                a0 = fmaxf(a0, cr[lane]      * ss);
                a1 = fmaxf(a1, cr[lane + 32] * ss);
                a2 = fmaxf(a2, cr[lane + 64] * ss);
                a3 = fmaxf(a3, cr[lane + 96] * ss);
            }
        }
        if (!any) { a0 = a1 = a2 = a3 = 0.f; }   // no kept in-edges -> 0
        float smi = smh[i];
        const float* ci = g_cur + i * 128;
        s_agg[w][lane] = a0; s_agg[w][lane + 32] = a1; s_agg[w][lane + 64] = a2; s_agg[w][lane + 96] = a3;
        s_xp[w][lane]      = ci[lane]      * smi;
        s_xp[w][lane + 32] = ci[lane + 32] * smi;
        s_xp[w][lane + 64] = ci[lane + 64] * smi;
        s_xp[w][lane + 96] = ci[lane + 96] * smi;
        __syncwarp();
        const float* wr = Wrel  + (h * 32 + lane) * 128;
        const float* wo = Wroot + (h * 32 + lane) * 128;
        float acc = bias[h * 32 + lane];
#pragma unroll 4
        for (int k = 0; k < 128; k++) acc += s_agg[w][k] * wr[k] + s_xp[w][k] * wo[k];
        g_new[i * 128 + h * 32 + lane] = lrelu(acc);
        __syncwarp();
    }
}

// ---------------- classifier gate on kept nodes only ----------------
__global__ void k_gate(const float* __restrict__ gW1, const float* __restrict__ gb1,
                       const float* __restrict__ gW2, const float* __restrict__ gb2) {
    __shared__ float s_xp[8][128];
    int c = blockIdx.y;
    int kc = g_kcount[c];
    int w = threadIdx.x >> 5, lane = threadIdx.x & 31;
    for (int entry = blockIdx.x * 8 + w; entry < kc; entry += gridDim.x * 8) {
        int i = g_klist[c * NND + entry];
        float smi = g_sm[c * NND + i];
        const float* ci = g_cur + i * 128;
        s_xp[w][lane]      = ci[lane]      * smi;
        s_xp[w][lane + 32] = ci[lane + 32] * smi;
        s_xp[w][lane + 64] = ci[lane + 64] * smi;
        s_xp[w][lane + 96] = ci[lane + 96] * smi;
        __syncwarp();
        float part = 0.f;
#pragma unroll
        for (int t4 = 0; t4 < 4; t4++) {
            int f = lane + t4 * 32;
            const float* w1 = gW1 + (c * 128 + f) * 128;
            float acc = gb1[c * 128 + f];
            for (int k = 0; k < 128; k++) acc += s_xp[w][k] * w1[k];
            part += lrelu(acc) * gW2[c * 128 + f];
        }
        for (int o = 16; o > 0; o >>= 1) part += __shfl_xor_sync(0xffffffffu, part, o);
        if (lane == 0) g_gate[c * NND + i] = part + gb2[c];
        __syncwarp();
    }
}

// ---------------- masked attention softmax + weighted pooling per graph ----------------
__global__ void k_attn_pool() {  // grid (B, 4) x 128
    __shared__ float sa[256];
    __shared__ float red[128];
    int c = blockIdx.y, g = blockIdx.x, t = threadIdx.x;
    int base = g * 256;
    int k0 = g_keep[c * NND + base + t];
    int k1 = g_keep[c * NND + base + t + 128];
    float gt0 = k0 ? g_gate[c * NND + base + t]       : 0.f;
    float gt1 = k1 ? g_gate[c * NND + base + t + 128] : 0.f;
    float m = -3.402823466e38f;
    if (k0) m = fmaxf(m, gt0);
    if (k1) m = fmaxf(m, gt1);
    red[t] = m; __syncthreads();
    for (int s = 64; s > 0; s >>= 1) { if (t < s) red[t] = fmaxf(red[t], red[t + s]); __syncthreads(); }
    float M = red[0]; __syncthreads();
    float es = 0.f;
    if (k0) es += expf(gt0 - M);
    if (k1) es += expf(gt1 - M);
    red[t] = es; __syncthreads();
    for (int s = 64; s > 0; s >>= 1) { if (t < s) red[t] += red[t + s]; __syncthreads(); }
    float S = red[0]; __syncthreads();
    float inv = 1.f / (S + 1e-16f);
    sa[t]       = k0 ? expf(gt0 - M) * inv * g_sm[c * NND + base + t]       : 0.f;
    sa[t + 128] = k1 ? expf(gt1 - M) * inv * g_sm[c * NND + base + t + 128] : 0.f;
    __syncthreads();
    float pf = 0.f;
    for (int j = 0; j < 256; j++) {
        float aj = sa[j];
        if (aj != 0.f) pf += aj * g_cur[(base + j) * 128 + t];
    }
    g_pooled[(c * BBD + g) * 128 + t] = pf;
}

// ---------------- final per-graph MLP -> logits ----------------
__global__ void k_final(const float* __restrict__ fW1, const float* __restrict__ fb1,
                        const float* __restrict__ fW2, const float* __restrict__ fb2) {
    __shared__ float sp[128];
    __shared__ float red[128];
    int c = blockIdx.y, g = blockIdx.x, t = threadIdx.x;
    sp[t] = g_pooled[(c * BBD + g) * 128 + t]; __syncthreads();
    const float* w1 = fW1 + (c * 128 + t) * 128;
    float acc = fb1[c * 128 + t];
    for (int k = 0; k < 128; k++) acc += sp[k] * w1[k];
    red[t] = lrelu(acc) * fW2[c * 128 + t]; __syncthreads();
    for (int s = 64; s > 0; s >>= 1) { if (t < s) red[t] += red[t + s]; __syncthreads(); }
    if (t == 0) g_logits[g * 4 + c] = red[0] + fb2[c];
}

__global__ void k_logsm(float* __restrict__ out) {  // 1 block x 256 graphs
    int g = threadIdx.x;
    float l0 = g_logits[g * 4 + 0], l1 = g_logits[g * 4 + 1];
    float l2 = g_logits[g * 4 + 2], l3 = g_logits[g * 4 + 3];
    float m = fmaxf(fmaxf(l0, l1), fmaxf(l2, l3));
    float s = expf(l0 - m) + expf(l1 - m) + expf(l2 - m) + expf(l3 - m);
    float ls = m + logf(s);
    out[g * 4 + 0] = l0 - ls;
    out[g * 4 + 1] = l1 - ls;
    out[g * 4 + 2] = l2 - ls;
    out[g * 4 + 3] = l3 - ls;
}

// ---------------------------------- launcher ----------------------------------
extern "C" void kernel_launch(void* const* d_in, const int* in_sizes, int n_in,
                              void* d_out, int out_size) {
    const float* x      = (const float*)d_in[0];
    const int*   ei     = (const int*)  d_in[1];
    const int*   src    = ei;
    const int*   dst    = ei + EED;
    const float* Wrel0  = (const float*)d_in[3];
    const float* Wroot0 = (const float*)d_in[4];
    const float* b0     = (const float*)d_in[5];
    const float* bn0g   = (const float*)d_in[6];
    const float* bn0b   = (const float*)d_in[7];
    const float* bpw    = (const float*)d_in[8];
    const float* bWrel  = (const float*)d_in[9];
    const float* bWroot = (const float*)d_in[10];
    const float* bbias  = (const float*)d_in[11];
    const float* bbng   = (const float*)d_in[12];
    const float* bbnb   = (const float*)d_in[13];
    const float* cpw    = (const float*)d_in[14];
    const float* gW1    = (const float*)d_in[15];
    const float* gb1    = (const float*)d_in[16];
    const float* gW2    = (const float*)d_in[17];
    const float* gb2    = (const float*)d_in[18];
    const float* fW1    = (const float*)d_in[19];
    const float* fb1    = (const float*)d_in[20];
    const float* fW2    = (const float*)d_in[21];
    const float* fb2    = (const float*)d_in[22];
    float* out = (float*)d_out;

    // CSR build (counting sort by dst)
    k_zero_cnt<<<NND / 256, 256>>>();
    k_hist<<<EED / 256, 256>>>(dst);
    k_scan1<<<256, 256>>>();
    k_scan2<<<1, 256>>>();
    k_scan3<<<256, 256>>>();
    k_scatter<<<EED / 256, 256>>>(src, dst);

    // conv0 -> lrelu -> bn0
    k_agg0<<<NND / 8, 256>>>(x);
    cudaFuncSetAttribute(k_conv0, cudaFuncAttributeMaxDynamicSharedMemorySize, 98304);
    k_conv0<<<NND / 64, 256, 98304>>>(x, Wrel0, Wroot0, b0);
    k_colstats<<<128, 128>>>();
    k_colfinal<<<1, 128>>>(bn0g);
    k_bn_apply<<<NND * EMBD / 256, 256>>>(bn0b);

    // 2 multi-head blocks
    for (int bi = 0; bi < 2; bi++) {
        k_init4<<<1, 32>>>();
        k_scores<<<NND / 8, 256>>>(bpw + bi * 4 * 128);
        k_softmax<<<dim3(BBD, 4), 256>>>(0.7f);
        k_zero_new<<<NND * EMBD / 4 / 256, 256>>>();
        k_head_out<<<dim3(256, 4), 256>>>(bWrel + bi * 4 * 32 * 128,
                                          bWroot + bi * 4 * 32 * 128,
                                          bbias + bi * 4 * 32);
        k_colstats<<<128, 128>>>();
        k_colfinal<<<1, 128>>>(bbng + bi * 128);
        k_residual<<<NND * EMBD / 256, 256>>>(bbnb + bi * 128);
    }

    // 4 classification heads
    k_init4<<<1, 32>>>();
    k_scores<<<NND / 8, 256>>>(cpw);
    k_softmax<<<dim3(BBD, 4), 256>>>(0.8f);
    k_gate<<<dim3(256, 4), 256>>>(gW1, gb1, gW2, gb2);
    k_attn_pool<<<dim3(BBD, 4), 128>>>();
    k_final<<<dim3(BBD, 4), 128>>>(fW1, fb1, fW2, fb2);
    k_logsm<<<1, 256>>>(out);
}

// round 4
// speedup vs baseline: 1.8050x; 1.8050x over previous
#include <cuda_runtime.h>

// Problem constants (fixed by the dataset)
#define NND   65536     // nodes
#define EED   524288    // edges
#define BBD   256       // graphs
#define EMBD  128
#define FEATD 64

// ---------------- scratch (static __device__ globals; no allocation) ----------------
__device__ float g_cur[NND * EMBD];     // current node features
__device__ float g_new[NND * EMBD];     // conv0 pre-BN output / per-block "new" buffer
__device__ float g_agg0[NND * FEATD];   // conv0 max-aggregation
__device__ int   g_off[NND + 1];        // CSR offsets (edges sorted by dst)
__device__ int   g_cnt[NND];            // histogram / scatter cursor
__device__ int   g_srcs[EED];           // CSR src list
__device__ int   g_bsum[256];           // scan block sums
__device__ float g_score[4 * NND];
__device__ float g_sm[4 * NND];
__device__ unsigned char g_keep[4 * NND];
__device__ int   g_klist[4 * NND];
__device__ int   g_kcount[4];
__device__ int   g_touch[NND];
__device__ float g_gate[4 * NND];
__device__ float g_partS[1024 * EMBD];  // column-stat partials
__device__ float g_partQ[1024 * EMBD];
__device__ float g_mean[EMBD];
__device__ float g_gamrs[EMBD];         // gamma * rsqrt(var + eps)
__device__ float g_pooled[4 * BBD * EMBD];
__device__ float g_logits[BBD * 4];

__device__ __forceinline__ float lrelu(float v) { return v > 0.f ? v : 0.01f * v; }

// ---------------- CSR build (counting sort of edges by dst) ----------------
__global__ void k_zero_cnt() { g_cnt[blockIdx.x * 256 + threadIdx.x] = 0; }

__global__ void k_hist(const int* __restrict__ dst) {
    int e = blockIdx.x * 256 + threadIdx.x;
    atomicAdd(&g_cnt[dst[e]], 1);
}

__global__ void k_scan1() {
    __shared__ int sh[256];
    int b = blockIdx.x, t = threadIdx.x;
    int v = g_cnt[b * 256 + t];
    sh[t] = v; __syncthreads();
    for (int ofs = 1; ofs < 256; ofs <<= 1) {
        int add = (t >= ofs) ? sh[t - ofs] : 0;
        __syncthreads(); sh[t] += add; __syncthreads();
    }
    g_off[b * 256 + t] = sh[t] - v;
    if (t == 255) g_bsum[b] = sh[255];
}

__global__ void k_scan2() {
    __shared__ int sh[256];
    int t = threadIdx.x;
    int v = g_bsum[t];
    sh[t] = v; __syncthreads();
    for (int ofs = 1; ofs < 256; ofs <<= 1) {
        int add = (t >= ofs) ? sh[t - ofs] : 0;
        __syncthreads(); sh[t] += add; __syncthreads();
    }
    g_bsum[t] = sh[t] - v;
}

__global__ void k_scan3() {
    int i = blockIdx.x * 256 + threadIdx.x;
    g_off[i] += g_bsum[i >> 8];
    g_cnt[i] = 0;
    if (i == 0) g_off[NND] = EED;
}

__global__ void k_scatter(const int* __restrict__ src, const int* __restrict__ dst) {
    int e = blockIdx.x * 256 + threadIdx.x;
    int d = dst[e];
    int p = atomicAdd(&g_cnt[d], 1);
    g_srcs[g_off[d] + p] = src[e];
}

// ---------------- conv0: warp-per-node max aggregation over in-edges ----------------
__global__ void k_agg0(const float* __restrict__ x) {
    int warp = (blockIdx.x * blockDim.x + threadIdx.x) >> 5;
    int lane = threadIdx.x & 31;
    if (warp >= NND) return;
    int o = g_off[warp], c = g_off[warp + 1] - o;
    float2 m = make_float2(-3.402823466e38f, -3.402823466e38f);
    for (int j = 0; j < c; j++) {
        int s = g_srcs[o + j];
        float2 v = *reinterpret_cast<const float2*>(x + s * FEATD + lane * 2);
        m.x = fmaxf(m.x, v.x); m.y = fmaxf(m.y, v.y);
    }
    if (!c) { m.x = 0.f; m.y = 0.f; }
    *reinterpret_cast<float2*>(g_agg0 + warp * FEATD + lane * 2) = m;
}

// ---------------- conv0 GEMM: new = lrelu([agg|x] @ [Wrel|Wroot]^T + b) + col stats ----------------
// 256 threads, tile 128 nodes x 128 feats, thread tile 8x8. smem: sA[k][n], sW[k][f], pad 132.
#define LDP 132
__global__ void __launch_bounds__(256) k_conv0(const float* __restrict__ x,
                                               const float* __restrict__ Wrel,
                                               const float* __restrict__ Wroot,
                                               const float* __restrict__ bias) {
    extern __shared__ float sh[];
    float* sA = sh;             // [128][LDP]
    float* sW = sh + 128 * LDP; // [128][LDP]
    int t = threadIdx.x;
    int nbase = blockIdx.x * 128;
    for (int idx = t; idx < 8192; idx += 256) {
        int f = idx >> 6, k = idx & 63;
        sW[k * LDP + f]        = Wrel[idx];
        sW[(k + 64) * LDP + f] = Wroot[idx];
    }
    for (int idx = t; idx < 8192; idx += 256) {
        int node = idx >> 6, k = idx & 63;
        sA[k * LDP + node]        = g_agg0[nbase * 64 + idx];
        sA[(k + 64) * LDP + node] = x[nbase * 64 + idx];
    }
    __syncthreads();
    int tx = t & 15, ty = t >> 4;
    int f0 = tx * 8, n0 = ty * 8;
    float acc[8][8];
#pragma unroll
    for (int i = 0; i < 8; i++)
#pragma unroll
        for (int j = 0; j < 8; j++) acc[i][j] = 0.f;
#pragma unroll 2
    for (int k = 0; k < 128; k++) {
        float4 a0 = *reinterpret_cast<float4*>(sA + k * LDP + n0);
        float4 a1 = *reinterpret_cast<float4*>(sA + k * LDP + n0 + 4);
        float4 w0 = *reinterpret_cast<float4*>(sW + k * LDP + f0);
        float4 w1 = *reinterpret_cast<float4*>(sW + k * LDP + f0 + 4);
        float av[8] = {a0.x, a0.y, a0.z, a0.w, a1.x, a1.y, a1.z, a1.w};
        float wv[8] = {w0.x, w0.y, w0.z, w0.w, w1.x, w1.y, w1.z, w1.w};
#pragma unroll
        for (int i = 0; i < 8; i++)
#pragma unroll
            for (int j = 0; j < 8; j++) acc[i][j] += av[i] * wv[j];
    }
    float bb[8], s[8], q[8];
#pragma unroll
    for (int j = 0; j < 8; j++) { bb[j] = bias[f0 + j]; s[j] = 0.f; q[j] = 0.f; }
#pragma unroll
    for (int i = 0; i < 8; i++) {
        float v[8];
#pragma unroll
        for (int j = 0; j < 8; j++) {
            v[j] = lrelu(acc[i][j] + bb[j]);
            s[j] += v[j]; q[j] += v[j] * v[j];
        }
        float4* outp = reinterpret_cast<float4*>(g_new + (size_t)(nbase + n0 + i) * 128 + f0);
        outp[0] = make_float4(v[0], v[1], v[2], v[3]);
        outp[1] = make_float4(v[4], v[5], v[6], v[7]);
    }
    // block-level column stats (deterministic order over ty)
    __syncthreads();
    float* sS = sA;             // [16][128]
    float* sQ = sA + 2048;
#pragma unroll
    for (int j = 0; j < 8; j++) { sS[ty * 128 + f0 + j] = s[j]; sQ[ty * 128 + f0 + j] = q[j]; }
    __syncthreads();
    if (t < 128) {
        float ss = 0.f, qq = 0.f;
        for (int r = 0; r < 16; r++) { ss += sS[r * 128 + t]; qq += sQ[r * 128 + t]; }
        g_partS[blockIdx.x * 128 + t] = ss;
        g_partQ[blockIdx.x * 128 + t] = qq;
    }
}

// finalize stats from nchunks partial rows
__global__ void k_colfinal(const float* __restrict__ gamma, int nchunks) {
    int col = threadIdx.x;
    float s = 0.f, q = 0.f;
    for (int c = 0; c < nchunks; c++) { s += g_partS[c * 128 + col]; q += g_partQ[c * 128 + col]; }
    float mean = s / (float)NND;
    float var  = q / (float)NND - mean * mean;
    g_mean[col]  = mean;
    g_gamrs[col] = gamma[col] * rsqrtf(var + 1e-5f);
}

// ---------------- fused BN-apply + pooling scores (and clears) ----------------
__global__ void __launch_bounds__(256) k_bn_scores(const float* __restrict__ beta,
                                                   const float* __restrict__ w4) {
    __shared__ float sw[512], s_m[128], s_g[128], s_b[128];
    int t = threadIdx.x;
    for (int i = t; i < 512; i += 256) sw[i] = w4[i];
    if (t < 128) { s_m[t] = g_mean[t]; s_g[t] = g_gamrs[t]; s_b[t] = beta[t]; }
    if (blockIdx.x == 0 && t < 4) g_kcount[t] = 0;
    if (t < 8) g_touch[blockIdx.x * 8 + t] = 0;
    __syncthreads();
    int w = t >> 5, lane = t & 31;
    int node = blockIdx.x * 8 + w;
    int f = lane * 4;
    float4 v = *reinterpret_cast<const float4*>(g_new + (size_t)node * 128 + f);
    float4 c;
    c.x = (v.x - s_m[f])     * s_g[f]     + s_b[f];
    c.y = (v.y - s_m[f + 1]) * s_g[f + 1] + s_b[f + 1];
    c.z = (v.z - s_m[f + 2]) * s_g[f + 2] + s_b[f + 2];
    c.w = (v.w - s_m[f + 3]) * s_g[f + 3] + s_b[f + 3];
    *reinterpret_cast<float4*>(g_cur + (size_t)node * 128 + f) = c;
#pragma unroll
    for (int h = 0; h < 4; h++) {
        const float* ww = sw + h * 128 + f;
        float p = c.x * ww[0] + c.y * ww[1] + c.z * ww[2] + c.w * ww[3];
        for (int o = 16; o > 0; o >>= 1) p += __shfl_xor_sync(0xffffffffu, p, o);
        if (lane == 0) g_score[h * NND + node] = p;
    }
}

// ---------------- fused residual + pooling scores (touch-sparse g_new read) ----------------
__global__ void __launch_bounds__(256) k_res_scores(const float* __restrict__ beta,
                                                    const float* __restrict__ w4) {
    __shared__ float sw[512], s_m[128], s_g[128], s_b[128];
    int t = threadIdx.x;
    for (int i = t; i < 512; i += 256) sw[i] = w4[i];
    if (t < 128) { s_m[t] = g_mean[t]; s_g[t] = g_gamrs[t]; s_b[t] = beta[t]; }
    if (blockIdx.x == 0 && t < 4) g_kcount[t] = 0;
    __syncthreads();
    int w = t >> 5, lane = t & 31;
    int node = blockIdx.x * 8 + w;
    int f = lane * 4;
    int tch = g_touch[node];
    float4 v = make_float4(0.f, 0.f, 0.f, 0.f);
    if (tch) v = *reinterpret_cast<const float4*>(g_new + (size_t)node * 128 + f);
    float4 cu = *reinterpret_cast<const float4*>(g_cur + (size_t)node * 128 + f);
    float4 c;
    c.x = 0.5f * cu.x + 0.25f * ((v.x - s_m[f])     * s_g[f]     + s_b[f]);
    c.y = 0.5f * cu.y + 0.25f * ((v.y - s_m[f + 1]) * s_g[f + 1] + s_b[f + 1]);
    c.z = 0.5f * cu.z + 0.25f * ((v.z - s_m[f + 2]) * s_g[f + 2] + s_b[f + 2]);
    c.w = 0.5f * cu.w + 0.25f * ((v.w - s_m[f + 3]) * s_g[f + 3] + s_b[f + 3]);
    *reinterpret_cast<float4*>(g_cur + (size_t)node * 128 + f) = c;
#pragma unroll
    for (int h = 0; h < 4; h++) {
        const float* ww = sw + h * 128 + f;
        float p = c.x * ww[0] + c.y * ww[1] + c.z * ww[2] + c.w * ww[3];
        for (int o = 16; o > 0; o >>= 1) p += __shfl_xor_sync(0xffffffffu, p, o);
        if (lane == 0) g_score[h * NND + node] = p;
    }
    __syncthreads();
    if (t < 8) g_touch[blockIdx.x * 8 + t] = 0;   // clear for next stage (after reads above)
}

// ---------------- per-graph softmax + keep + compaction + kept-row prep ----------------
__global__ void k_softmax(float minscore, int doPrep) {  // grid (B, 4) x 256
    __shared__ float red[256];
    __shared__ int slist[256];
    __shared__ int scnt;
    int g = blockIdx.x, h = blockIdx.y, t = threadIdx.x;
    if (t == 0) scnt = 0;
    int i = g * 256 + t;
    float s = g_score[h * NND + i];
    red[t] = s; __syncthreads();
    for (int st = 128; st > 0; st >>= 1) { if (t < st) red[t] = fmaxf(red[t], red[t + st]); __syncthreads(); }
    float m = red[0]; __syncthreads();
    float e = expf(s - m);
    red[t] = e; __syncthreads();
    for (int st = 128; st > 0; st >>= 1) { if (t < st) red[t] += red[t + st]; __syncthreads(); }
    float S = red[0]; __syncthreads();
    float sm = e / (S + 1e-16f);
    red[t] = sm; __syncthreads();
    for (int st = 128; st > 0; st >>= 1) { if (t < st) red[t] = fmaxf(red[t], red[t + st]); __syncthreads(); }
    float smax = red[0];
    float thr = fminf(smax - 1e-7f, minscore);
    bool keep = sm > thr;
    g_sm[h * NND + i] = sm;
    g_keep[h * NND + i] = keep ? 1 : 0;
    if (keep) {
        int p = atomicAdd(&g_kcount[h], 1);
        g_klist[h * NND + p] = i;
        int lp = atomicAdd(&scnt, 1);
        slist[lp] = t;
    }
    __syncthreads();
    if (doPrep) {
        int n = scnt;
        for (int li = 0; li < n; li++) {
            int node = g * 256 + slist[li];
            if (t < 128) g_new[(size_t)node * 128 + t] = 0.f;
            if (t == 0) g_touch[node] = 1;
        }
    }
}

// ---------------- block head conv on kept nodes only (warp per kept node) ----------------
__global__ void k_head_out(const float* __restrict__ Wrel, const float* __restrict__ Wroot,
                           const float* __restrict__ bias) {  // grid (32, 4) x 256
    __shared__ float s_agg[8][128];
    __shared__ float s_xp[8][128];
    int h = blockIdx.y;
    int kc = g_kcount[h];
    int w = threadIdx.x >> 5, lane = threadIdx.x & 31;
    const float* smh = g_sm + h * NND;
    const unsigned char* kph = g_keep + h * NND;
    for (int entry = blockIdx.x * 8 + w; entry < kc; entry += gridDim.x * 8) {
        int i = g_klist[h * NND + entry];
        int o = g_off[i];
        int c = g_off[i + 1] - o;
        float a0 = -3.402823466e38f, a1 = a0, a2 = a0, a3 = a0;
        bool any = false;
        for (int j = 0; j < c; j++) {
            int s = g_srcs[o + j];
            if (kph[s]) {
                any = true;
                float ss = smh[s];
                const float* cr = g_cur + (size_t)s * 128;
                a0 = fmaxf(a0, cr[lane]      * ss);
                a1 = fmaxf(a1, cr[lane + 32] * ss);
                a2 = fmaxf(a2, cr[lane + 64] * ss);
                a3 = fmaxf(a3, cr[lane + 96] * ss);
            }
        }
        if (!any) { a0 = a1 = a2 = a3 = 0.f; }
        float smi = smh[i];
        const float* ci = g_cur + (size_t)i * 128;
        s_agg[w][lane] = a0; s_agg[w][lane + 32] = a1; s_agg[w][lane + 64] = a2; s_agg[w][lane + 96] = a3;
        s_xp[w][lane]      = ci[lane]      * smi;
        s_xp[w][lane + 32] = ci[lane + 32] * smi;
        s_xp[w][lane + 64] = ci[lane + 64] * smi;
        s_xp[w][lane + 96] = ci[lane + 96] * smi;
        __syncwarp();
        const float* wr = Wrel  + (h * 32 + lane) * 128;
        const float* wo = Wroot + (h * 32 + lane) * 128;
        float acc = bias[h * 32 + lane];
#pragma unroll 4
        for (int k = 0; k < 128; k++) acc += s_agg[w][k] * wr[k] + s_xp[w][k] * wo[k];
        g_new[(size_t)i * 128 + h * 32 + lane] = lrelu(acc);
        __syncwarp();
    }
}

// ---------------- kept-row column stats (deterministic: node order fixed) ----------------
__global__ void k_statsK() {  // grid (32, 4) x 256; warp per graph
    int h = blockIdx.y;
    int w = threadIdx.x >> 5, lane = threadIdx.x & 31;
    int g = blockIdx.x * 8 + w;
    const unsigned int* kp = reinterpret_cast<const unsigned int*>(g_keep + h * NND + g * 256);
    int col = h * 32 + lane;
    float s = 0.f, q = 0.f;
    for (int n4 = 0; n4 < 64; n4++) {
        unsigned int u = kp[n4];
        if (u) {
#pragma unroll
            for (int b = 0; b < 4; b++) {
                if ((u >> (8 * b)) & 0xff) {
                    float v = g_new[(size_t)(g * 256 + n4 * 4 + b) * 128 + col];
                    s += v; q += v * v;
                }
            }
        }
    }
    g_partS[(h * 256 + g) * 32 + lane] = s;
    g_partQ[(h * 256 + g) * 32 + lane] = q;
}

__global__ void k_colfinal2(const float* __restrict__ gamma) {  // 1 x 128
    int f = threadIdx.x;
    int h = f >> 5, c = f & 31;
    float s = 0.f, q = 0.f;
    for (int g = 0; g < 256; g++) {
        s += g_partS[(h * 256 + g) * 32 + c];
        q += g_partQ[(h * 256 + g) * 32 + c];
    }
    float mean = s / (float)NND;
    float var  = q / (float)NND - mean * mean;
    g_mean[f]  = mean;
    g_gamrs[f] = gamma[f] * rsqrtf(var + 1e-5f);
}

// ---------------- classifier gate on kept nodes only ----------------
__global__ void k_gate(const float* __restrict__ gW1, const float* __restrict__ gb1,
                       const float* __restrict__ gW2, const float* __restrict__ gb2) {
    __shared__ float s_xp[8][128];
    int c = blockIdx.y;
    int kc = g_kcount[c];
    int w = threadIdx.x >> 5, lane = threadIdx.x & 31;
    for (int entry = blockIdx.x * 8 + w; entry < kc; entry += gridDim.x * 8) {
        int i = g_klist[c * NND + entry];
        float smi = g_sm[c * NND + i];
        const float* ci = g_cur + (size_t)i * 128;
        s_xp[w][lane]      = ci[lane]      * smi;
        s_xp[w][lane + 32] = ci[lane + 32] * smi;
        s_xp[w][lane + 64] = ci[lane + 64] * smi;
        s_xp[w][lane + 96] = ci[lane + 96] * smi;
        __syncwarp();
        float part = 0.f;
#pragma unroll
        for (int t4 = 0; t4 < 4; t4++) {
            int f = lane + t4 * 32;
            const float* w1 = gW1 + (c * 128 + f) * 128;
            float acc = gb1[c * 128 + f];
            for (int k = 0; k < 128; k++) acc += s_xp[w][k] * w1[k];
            part += lrelu(acc) * gW2[c * 128 + f];
        }
        for (int o = 16; o > 0; o >>= 1) part += __shfl_xor_sync(0xffffffffu, part, o);
        if (lane == 0) g_gate[c * NND + i] = part + gb2[c];
        __syncwarp();
    }
}

// ---------------- masked attention softmax + weighted pooling per graph ----------------
__global__ void k_attn_pool() {  // grid (B, 4) x 128
    __shared__ float sa[256];
    __shared__ float red[128];
    int c = blockIdx.y, g = blockIdx.x, t = threadIdx.x;
    int base = g * 256;
    int k0 = g_keep[c * NND + base + t];
    int k1 = g_keep[c * NND + base + t + 128];
    float gt0 = k0 ? g_gate[c * NND + base + t]       : 0.f;
    float gt1 = k1 ? g_gate[c * NND + base + t + 128] : 0.f;
    float m = -3.402823466e38f;
    if (k0) m = fmaxf(m, gt0);
    if (k1) m = fmaxf(m, gt1);
    red[t] = m; __syncthreads();
    for (int s = 64; s > 0; s >>= 1) { if (t < s) red[t] = fmaxf(red[t], red[t + s]); __syncthreads(); }
    float M = red[0]; __syncthreads();
    float es = 0.f;
    if (k0) es += expf(gt0 - M);
    if (k1) es += expf(gt1 - M);
    red[t] = es; __syncthreads();
    for (int s = 64; s > 0; s >>= 1) { if (t < s) red[t] += red[t + s]; __syncthreads(); }
    float S = red[0]; __syncthreads();
    float inv = 1.f / (S + 1e-16f);
    sa[t]       = k0 ? expf(gt0 - M) * inv * g_sm[c * NND + base + t]       : 0.f;
    sa[t + 128] = k1 ? expf(gt1 - M) * inv * g_sm[c * NND + base + t + 128] : 0.f;
    __syncthreads();
    float pf = 0.f;
    for (int j = 0; j < 256; j++) {
        float aj = sa[j];
        if (aj != 0.f) pf += aj * g_cur[(size_t)(base + j) * 128 + t];
    }
    g_pooled[(c * BBD + g) * 128 + t] = pf;
}

// ---------------- final per-graph MLP -> logits ----------------
__global__ void k_final(const float* __restrict__ fW1, const float* __restrict__ fb1,
                        const float* __restrict__ fW2, const float* __restrict__ fb2) {
    __shared__ float sp[128];
    __shared__ float red[128];
    int c = blockIdx.y, g = blockIdx.x, t = threadIdx.x;
    sp[t] = g_pooled[(c * BBD + g) * 128 + t]; __syncthreads();
    const float* w1 = fW1 + (c * 128 + t) * 128;
    float acc = fb1[c * 128 + t];
    for (int k = 0; k < 128; k++) acc += sp[k] * w1[k];
    red[t] = lrelu(acc) * fW2[c * 128 + t]; __syncthreads();
    for (int s = 64; s > 0; s >>= 1) { if (t < s) red[t] += red[t + s]; __syncthreads(); }
    if (t == 0) g_logits[g * 4 + c] = red[0] + fb2[c];
}

__global__ void k_logsm(float* __restrict__ out) {  // 1 x 256
    int g = threadIdx.x;
    float l0 = g_logits[g * 4 + 0], l1 = g_logits[g * 4 + 1];
    float l2 = g_logits[g * 4 + 2], l3 = g_logits[g * 4 + 3];
    float m = fmaxf(fmaxf(l0, l1), fmaxf(l2, l3));
    float s = expf(l0 - m) + expf(l1 - m) + expf(l2 - m) + expf(l3 - m);
    float ls = m + logf(s);
    out[g * 4 + 0] = l0 - ls;
    out[g * 4 + 1] = l1 - ls;
    out[g * 4 + 2] = l2 - ls;
    out[g * 4 + 3] = l3 - ls;
}

// ---------------------------------- launcher ----------------------------------
extern "C" void kernel_launch(void* const* d_in, const int* in_sizes, int n_in,
                              void* d_out, int out_size) {
    const float* x      = (const float*)d_in[0];
    const int*   ei     = (const int*)  d_in[1];
    const int*   src    = ei;
    const int*   dst    = ei + EED;
    const float* Wrel0  = (const float*)d_in[3];
    const float* Wroot0 = (const float*)d_in[4];
    const float* b0     = (const float*)d_in[5];
    const float* bn0g   = (const float*)d_in[6];
    const float* bn0b   = (const float*)d_in[7];
    const float* bpw    = (const float*)d_in[8];
    const float* bWrel  = (const float*)d_in[9];
    const float* bWroot = (const float*)d_in[10];
    const float* bbias  = (const float*)d_in[11];
    const float* bbng   = (const float*)d_in[12];
    const float* bbnb   = (const float*)d_in[13];
    const float* cpw    = (const float*)d_in[14];
    const float* gW1    = (const float*)d_in[15];
    const float* gb1    = (const float*)d_in[16];
    const float* gW2    = (const float*)d_in[17];
    const float* gb2    = (const float*)d_in[18];
    const float* fW1    = (const float*)d_in[19];
    const float* fb1    = (const float*)d_in[20];
    const float* fW2    = (const float*)d_in[21];
    const float* fb2    = (const float*)d_in[22];
    float* out = (float*)d_out;

    // CSR build
    k_zero_cnt<<<NND / 256, 256>>>();
    k_hist<<<EED / 256, 256>>>(dst);
    k_scan1<<<256, 256>>>();
    k_scan2<<<1, 256>>>();
    k_scan3<<<256, 256>>>();
    k_scatter<<<EED / 256, 256>>>(src, dst);

    // conv0 -> lrelu (+fused stats) -> finalize -> bn+scores(block0)
    k_agg0<<<NND / 8, 256>>>(x);
    static int smem_set = 0;
    if (!smem_set) {
        cudaFuncSetAttribute(k_conv0, cudaFuncAttributeMaxDynamicSharedMemorySize,
                             2 * 128 * LDP * 4);
        smem_set = 1;
    }
    k_conv0<<<NND / 128, 256, 2 * 128 * LDP * 4>>>(x, Wrel0, Wroot0, b0);
    k_colfinal<<<1, 128>>>(bn0g, NND / 128);
    k_bn_scores<<<NND / 8, 256>>>(bn0b, bpw);          // scores for block 0

    // 2 multi-head blocks
    for (int bi = 0; bi < 2; bi++) {
        k_softmax<<<dim3(BBD, 4), 256>>>(0.7f, 1);
        k_head_out<<<dim3(32, 4), 256>>>(bWrel + bi * 4 * 32 * 128,
                                         bWroot + bi * 4 * 32 * 128,
                                         bbias + bi * 4 * 32);
        k_statsK<<<dim3(32, 4), 256>>>();
        k_colfinal2<<<1, 128>>>(bbng + bi * 128);
        // residual + scores for the NEXT stage (block1 pool w, then classifier pool w)
        const float* nextw = (bi == 0) ? (bpw + 4 * 128) : cpw;
        k_res_scores<<<NND / 8, 256>>>(bbnb + bi * 128, nextw);
    }

    // 4 classification heads
    k_softmax<<<dim3(BBD, 4), 256>>>(0.8f, 0);
    k_gate<<<dim3(32, 4), 256>>>(gW1, gb1, gW2, gb2);
    k_attn_pool<<<dim3(BBD, 4), 128>>>();
    k_final<<<dim3(BBD, 4), 128>>>(fW1, fb1, fW2, fb2);
    k_logsm<<<1, 256>>>(out);
}